// round 14
// baseline (speedup 1.0000x reference)
#include <cuda_runtime.h>
#include <cstdint>

#define B_N   65536
#define CTXD  384
#define NPR   5
#define MEMV  10
#define EPSV  1e-8f
#define NPART 296

typedef unsigned long long ull;

__device__ float g_part[NPART];
__device__ float g_const_f[192];
__device__ float g_const_r[192];
__device__ float g_M[NPR * CTXD];
__device__ float g_lb[NPR];

__device__ __forceinline__ ull pack2(float lo, float hi) {
    ull r; asm("mov.b64 %0,{%1,%2};" : "=l"(r) : "f"(lo), "f"(hi)); return r;
}
__device__ __forceinline__ float2 unpack2(ull v) {
    float2 f; asm("mov.b64 {%0,%1},%2;" : "=f"(f.x), "=f"(f.y) : "l"(v)); return f;
}
__device__ __forceinline__ void fma2(ull& acc, ull a, ull b) {
    asm("fma.rn.f32x2 %0,%1,%2,%0;" : "+l"(acc) : "l"(a), "l"(b));
}
__device__ __forceinline__ float hadd2(ull v) { float2 f = unpack2(v); return f.x + f.y; }
__device__ __forceinline__ float wsum(float v) {
#pragma unroll
    for (int o = 16; o; o >>= 1) v += __shfl_xor_sync(0xffffffffu, v, o);
    return v;
}
__device__ __forceinline__ float sigm(float x) { return __fdividef(1.0f, 1.0f + __expf(-x)); }
__device__ __forceinline__ float ftanh(float x) { return 1.0f - __fdividef(2.0f, 1.0f + __expf(2.0f * x)); }

__device__ __forceinline__ void load_row_pairs(const float* p, ull* dst) {
    const float4* v = (const float4*)p;
#pragma unroll
    for (int k = 0; k < 8; k++) {
        float4 a = v[k], b = v[k + 8];
        dst[k * 4 + 0] = pack2(a.x, b.x);
        dst[k * 4 + 1] = pack2(a.y, b.y);
        dst[k * 4 + 2] = pack2(a.z, b.z);
        dst[k * 4 + 3] = pack2(a.w, b.w);
    }
}

// load QUARTER of a row (K-pairs kq*8 .. kq*8+7) as 8 packed pairs
__device__ __forceinline__ void load_quarter_pairs(const float* p, int kq, ull* dst) {
    const float4* v = (const float4*)p;
    float4 a = v[kq * 2], b = v[kq * 2 + 1];
    float4 c = v[8 + kq * 2], d = v[8 + kq * 2 + 1];
    dst[0] = pack2(a.x, c.x); dst[1] = pack2(a.y, c.y);
    dst[2] = pack2(a.z, c.z); dst[3] = pack2(a.w, c.w);
    dst[4] = pack2(b.x, d.x); dst[5] = pack2(b.y, d.y);
    dst[6] = pack2(b.z, d.z); dst[7] = pack2(b.w, d.w);
}

// ---------------- kA: batch-constant MHA branch + GRU constant fold ----------------
__global__ void kA(const float* __restrict__ memory, const float* __restrict__ tw,
                   const float* __restrict__ ipw, const float* __restrict__ ipb,
                   const float* __restrict__ ow, const float* __restrict__ ob,
                   const float* __restrict__ wih_f, const float* __restrict__ bih_f,
                   const float* __restrict__ wih_r, const float* __restrict__ bih_r) {
    __shared__ float mt[64], vv[64], ov[64];
    int t = threadIdx.x;  // 192 threads
    if (t < 64) {
        float a[MEMV], m = -1e30f, s = 0.f;
#pragma unroll
        for (int i = 0; i < MEMV; i++) { a[i] = tw[i]; m = fmaxf(m, a[i]); }
#pragma unroll
        for (int i = 0; i < MEMV; i++) { a[i] = __expf(a[i] - m); s += a[i]; }
        float inv = 1.f / s, acc = 0.f;
#pragma unroll
        for (int i = 0; i < MEMV; i++) acc += (a[i] * inv) * memory[i * 64 + t];
        mt[t] = acc;
    }
    __syncthreads();
    if (t < 64) {
        float v = ipb[128 + t];
        for (int j = 0; j < 64; j++) v += mt[j] * ipw[(128 + t) * 64 + j];
        vv[t] = v;
    }
    __syncthreads();
    if (t < 64) {
        float o = ob[t];
        for (int j = 0; j < 64; j++) o += vv[j] * ow[t * 64 + j];
        ov[t] = o;
    }
    __syncthreads();
    float af = bih_f[t], ar = bih_r[t];
    for (int j = 0; j < 64; j++) {
        float o = ov[j];
        af += wih_f[t * 130 + j] * o;
        ar += wih_r[t * 130 + j] * o;
    }
    g_const_f[t] = af;
    g_const_r[t] = ar;
}

// ---------------- kM: fold ctx GEMM into logit matrix M = idw_c @ ctx_w ----------------
__global__ void kM(const float* __restrict__ ideal_w, const float* __restrict__ ideal_b,
                   const float* __restrict__ ctx_w, const float* __restrict__ ctx_b) {
    int idx = blockIdx.x * 128 + threadIdx.x;
    if (idx < NPR * CTXD) {
        int p = idx / CTXD, k = idx - p * CTXD;
        float s = 0.f;
        for (int d = 0; d < 64; d++)
            s += ideal_w[p * 128 + 64 + d] * ctx_w[d * CTXD + k];
        g_M[idx] = s;
    }
    if (idx < NPR) {
        float s = ideal_b[idx];
        for (int d = 0; d < 64; d++)
            s += ideal_w[idx * 128 + 64 + d] * ctx_b[d];
        g_lb[idx] = s;
    }
}

// ---------------- kB1: prime logits (via M) + softmax + scalars (2 rows/lane) ----------------
#define B1_M    0        // 1920 f
#define B1_IDWT 1920     // 160 ull = 320 f
#define B1_PE   2240     // 160 ull
#define B1_PREV 2560     // 32 ull
#define B1_LB   2624     // 8
#define B1_PART 2632     // 4
#define SMEM_B1_BYTES (2640 * 4)

__global__ __launch_bounds__(128, 2)
void kB1(const float* __restrict__ theta, const float* __restrict__ context,
         const float* __restrict__ ideal_w,
         const float* __restrict__ prime_embeds, const float* __restrict__ prev_ideal,
         const float* __restrict__ freq_w, const float* __restrict__ freq_b,
         float* __restrict__ out) {
    extern __shared__ float smem[];
    const int tid = threadIdx.x, lane = tid & 31, wrp = tid >> 5;

    float* Ms = smem + B1_M;
    ull* idwt = (ull*)(smem + B1_IDWT);
    ull* pe_s = (ull*)(smem + B1_PE);
    ull* prev_s = (ull*)(smem + B1_PREV);
    float* s_lb = smem + B1_LB;
    float* s_part = smem + B1_PART;

    for (int idx = tid; idx < NPR * CTXD; idx += 128) Ms[idx] = g_M[idx];
    for (int idx = tid; idx < 160; idx += 128) {
        int p = idx >> 5, j = idx & 31;
        idwt[idx] = pack2(ideal_w[p * 128 + j], ideal_w[p * 128 + j + 32]);
        pe_s[idx] = pack2(prime_embeds[p * 64 + j], prime_embeds[p * 64 + j + 32]);
    }
    if (tid < 32) prev_s[tid] = pack2(prev_ideal[tid], prev_ideal[tid + 32]);
    if (tid < NPR) s_lb[tid] = g_lb[tid];
    __syncthreads();

    const float fwv = freq_w[0], fbv = freq_b[0];
    float* out_rs = out + (size_t)4 * B_N * 64;
    float* out_om = out_rs + B_N;
    float* out_pw = out_om + B_N;

    const int u = blockIdx.x * 4 + wrp;
    float stress_total = 0.f;
    if (u < 1024) {
        const int r0 = u * 64 + lane, r1 = r0 + 32;

        float lg0[NPR], lg1[NPR];
#pragma unroll
        for (int p = 0; p < NPR; p++) { lg0[p] = s_lb[p]; lg1[p] = s_lb[p]; }
        const float4* x0v = (const float4*)(context + (size_t)r0 * CTXD);
        const float4* x1v = (const float4*)(context + (size_t)r1 * CTXD);
#pragma unroll 4
        for (int k4 = 0; k4 < 96; k4++) {
            float4 a0 = x0v[k4], a1 = x1v[k4];
#pragma unroll
            for (int p = 0; p < NPR; p++) {
                float4 m = ((const float4*)(Ms + p * CTXD))[k4];
                lg0[p] += m.x * a0.x + m.y * a0.y + m.z * a0.z + m.w * a0.w;
                lg1[p] += m.x * a1.x + m.y * a1.y + m.z * a1.z + m.w * a1.w;
            }
        }

        ull th0[32], th1[32];
        load_row_pairs(theta + (size_t)r0 * 64, th0);
        load_row_pairs(theta + (size_t)r1 * 64, th1);
#pragma unroll
        for (int p5 = 0; p5 < NPR; p5++) {
            ull a = 0, b = 0;
#pragma unroll
            for (int j = 0; j < 32; j++) {
                ull w = idwt[p5 * 32 + j];
                fma2(a, w, th0[j]);
                fma2(b, w, th1[j]);
            }
            lg0[p5] += hadd2(a);
            lg1[p5] += hadd2(b);
        }

        float pw0[NPR], pw1[NPR];
        {
            float m0 = lg0[0], m1 = lg1[0];
#pragma unroll
            for (int p = 1; p < NPR; p++) { m0 = fmaxf(m0, lg0[p]); m1 = fmaxf(m1, lg1[p]); }
            float s0 = 0.f, s1 = 0.f;
#pragma unroll
            for (int p = 0; p < NPR; p++) {
                pw0[p] = __expf(lg0[p] - m0); s0 += pw0[p];
                pw1[p] = __expf(lg1[p] - m1); s1 += pw1[p];
            }
            float i0 = __fdividef(1.f, s0), i1 = __fdividef(1.f, s1);
#pragma unroll
            for (int p = 0; p < NPR; p++) {
                pw0[p] *= i0; pw1[p] *= i1;
                out_pw[(size_t)r0 * NPR + p] = pw0[p];
                out_pw[(size_t)r1 * NPR + p] = pw1[p];
            }
        }

        float str0 = 0.f, nth0 = 0.f, nti0 = 0.f, rd0 = 0.f, f20 = 0.f;
        float str1 = 0.f, nth1 = 0.f, nti1 = 0.f, rd1 = 0.f, f21 = 0.f;
#pragma unroll
        for (int j = 0; j < 32; j++) {
            float2 pv = unpack2(prev_s[j]);
            float2 pe0 = unpack2(pe_s[0 * 32 + j]);
            float2 pe1 = unpack2(pe_s[1 * 32 + j]);
            float2 pe2 = unpack2(pe_s[2 * 32 + j]);
            float2 pe3 = unpack2(pe_s[3 * 32 + j]);
            float2 pe4 = unpack2(pe_s[4 * 32 + j]);
            {
                float tix = pw0[0] * pe0.x + pw0[1] * pe1.x + pw0[2] * pe2.x
                          + pw0[3] * pe3.x + pw0[4] * pe4.x;
                float tiy = pw0[0] * pe0.y + pw0[1] * pe1.y + pw0[2] * pe2.y
                          + pw0[3] * pe3.y + pw0[4] * pe4.y;
                float2 t = unpack2(th0[j]);
                float dx = t.x - tix, dy = t.y - tiy;
                str0 += dx * dx + dy * dy;
                nth0 += t.x * t.x + t.y * t.y;
                nti0 += tix * tix + tiy * tiy;
                rd0  += t.x * tix + t.y * tiy;
                float px = tix - pv.x, py = tiy - pv.y;
                f20 += px * px + py * py;
            }
            {
                float tix = pw1[0] * pe0.x + pw1[1] * pe1.x + pw1[2] * pe2.x
                          + pw1[3] * pe3.x + pw1[4] * pe4.x;
                float tiy = pw1[0] * pe0.y + pw1[1] * pe1.y + pw1[2] * pe2.y
                          + pw1[3] * pe3.y + pw1[4] * pe4.y;
                float2 t = unpack2(th1[j]);
                float dx = t.x - tix, dy = t.y - tiy;
                str1 += dx * dx + dy * dy;
                nth1 += t.x * t.x + t.y * t.y;
                nti1 += tix * tix + tiy * tiy;
                rd1  += t.x * tix + t.y * tiy;
                float px = tix - pv.x, py = tiy - pv.y;
                f21 += px * px + py * py;
            }
        }
        {
            float it0 = __fdividef(1.f, sqrtf(nth0) + EPSV);
            float ii0 = __fdividef(1.f, sqrtf(nti0) + EPSV);
            out_rs[r0] = __fdividef(rd0 * it0 * ii0,
                                    fmaxf(sqrtf(nth0) * it0 * sqrtf(nti0) * ii0, EPSV));
            float fr0 = sqrtf(f20);
            out_om[r0] = ftanh(fr0 * fwv + fbv) * (1.0f + 0.1f * __sinf(fr0));
            float it1 = __fdividef(1.f, sqrtf(nth1) + EPSV);
            float ii1 = __fdividef(1.f, sqrtf(nti1) + EPSV);
            out_rs[r1] = __fdividef(rd1 * it1 * ii1,
                                    fmaxf(sqrtf(nth1) * it1 * sqrtf(nti1) * ii1, EPSV));
            float fr1 = sqrtf(f21);
            out_om[r1] = ftanh(fr1 * fwv + fbv) * (1.0f + 0.1f * __sinf(fr1));
        }
        stress_total = str0 + str1;
    }

    float ws = wsum(stress_total);
    if (lane == 0) s_part[wrp] = ws;
    __syncthreads();
    if (tid == 0) {
        g_part[blockIdx.x] = (s_part[0] + s_part[1]) + (s_part[2] + s_part[3]);
    }
}

// ---------------- kB2a: emotion MLP -> out_e = relu(..) + 0.001*stress ----------------
#define B2A_W1  0        // 4096 ull
#define B2A_W2  8192     // 4096 ull
#define B2A_B1  16384    // 128
#define B2A_B2  16512    // 64
#define B2A_STC 16576    // 1
#define SMEM_B2A_BYTES (16580 * 4)

__global__ __launch_bounds__(128, 3)
void kB2a(const float* __restrict__ theta,
          const float* __restrict__ emo_w1, const float* __restrict__ emo_b1,
          const float* __restrict__ emo_w2, const float* __restrict__ emo_b2,
          float* __restrict__ out) {
    extern __shared__ float smem[];
    const int tid = threadIdx.x, lane = tid & 31, wrp = tid >> 5;
    ull* w1i = (ull*)(smem + B2A_W1);
    ull* w2i = (ull*)(smem + B2A_W2);
    float* s_b1 = smem + B2A_B1;
    float* s_b2 = smem + B2A_B2;
    float* s_stc = smem + B2A_STC;

    for (int idx = tid; idx < 4096; idx += 128) {
        int oi = idx & 7, j = (idx >> 3) & 31, og = idx >> 8;
        int o = og * 8 + oi;
        w1i[idx] = pack2(emo_w1[o * 64 + j], emo_w1[o * 64 + j + 32]);
    }
    for (int idx = tid; idx < 4096; idx += 128) {
        int di = idx & 31, kh = idx >> 5;
        w2i[idx] = pack2(emo_w2[di * 128 + kh], emo_w2[(di + 32) * 128 + kh]);
    }
    if (tid < 128) s_b1[tid] = emo_b1[tid];
    if (tid < 64) s_b2[tid] = emo_b2[tid];
    if (tid == 0) {
        float s = 0.f;
        for (int b = 0; b < NPART; b++) s += g_part[b];
        s_stc[0] = 0.001f * s;
    }
    __syncthreads();
    const float stc = s_stc[0];

    float* out_e = out + (size_t)3 * B_N * 64;

#pragma unroll 1
    for (int u = blockIdx.x * 4 + wrp; u < 2048; u += 444 * 4) {
        const int r = u * 32 + lane;
        const size_t ro = (size_t)r * 64;

        ull th_p[32];
        load_row_pairs(theta + ro, th_p);

        ull e_acc[32];
#pragma unroll
        for (int di = 0; di < 32; di++) e_acc[di] = pack2(s_b2[di], s_b2[di + 32]);
#pragma unroll 1
        for (int og = 0; og < 16; og++) {
            const ulonglong2* w1v = (const ulonglong2*)(w1i + og * 256);
            ull a0 = 0, a1 = 0, a2 = 0, a3 = 0, a4 = 0, a5 = 0, a6 = 0, a7 = 0;
#pragma unroll
            for (int j = 0; j < 32; j++) {
                ulonglong2 p0 = w1v[j * 4 + 0], p1 = w1v[j * 4 + 1];
                ulonglong2 p2 = w1v[j * 4 + 2], p3 = w1v[j * 4 + 3];
                ull t = th_p[j];
                fma2(a0, p0.x, t); fma2(a1, p0.y, t);
                fma2(a2, p1.x, t); fma2(a3, p1.y, t);
                fma2(a4, p2.x, t); fma2(a5, p2.y, t);
                fma2(a6, p3.x, t); fma2(a7, p3.y, t);
            }
            float t8[8];
            t8[0] = ftanh(hadd2(a0) + s_b1[og * 8 + 0]);
            t8[1] = ftanh(hadd2(a1) + s_b1[og * 8 + 1]);
            t8[2] = ftanh(hadd2(a2) + s_b1[og * 8 + 2]);
            t8[3] = ftanh(hadd2(a3) + s_b1[og * 8 + 3]);
            t8[4] = ftanh(hadd2(a4) + s_b1[og * 8 + 4]);
            t8[5] = ftanh(hadd2(a5) + s_b1[og * 8 + 5]);
            t8[6] = ftanh(hadd2(a6) + s_b1[og * 8 + 6]);
            t8[7] = ftanh(hadd2(a7) + s_b1[og * 8 + 7]);
#pragma unroll
            for (int k = 0; k < 8; k++) {
                ull tt = pack2(t8[k], t8[k]);
                const ulonglong2* w2v = (const ulonglong2*)(w2i + (og * 8 + k) * 32);
#pragma unroll
                for (int di2 = 0; di2 < 16; di2++) {
                    ulonglong2 q = w2v[di2];
                    fma2(e_acc[di2 * 2 + 0], q.x, tt);
                    fma2(e_acc[di2 * 2 + 1], q.y, tt);
                }
            }
        }
        float4* ep = (float4*)(out_e + ro);
#pragma unroll
        for (int k = 0; k < 8; k++) {
            float2 v0 = unpack2(e_acc[k * 4 + 0]);
            float2 v1 = unpack2(e_acc[k * 4 + 1]);
            float2 v2 = unpack2(e_acc[k * 4 + 2]);
            float2 v3 = unpack2(e_acc[k * 4 + 3]);
            ep[k]     = make_float4(fmaxf(v0.x, 0.f) + stc, fmaxf(v1.x, 0.f) + stc,
                                    fmaxf(v2.x, 0.f) + stc, fmaxf(v3.x, 0.f) + stc);
            ep[8 + k] = make_float4(fmaxf(v0.y, 0.f) + stc, fmaxf(v1.y, 0.f) + stc,
                                    fmaxf(v2.y, 0.f) + stc, fmaxf(v3.y, 0.f) + stc);
        }
    }
}

// ---------------- kDF v3: fused GRU, quarter-K split (conflict-free), 2 rows/lane ----------------
// u2 layout: wEH2[((d*8 + jj)*4 + kq)*6 + s2]; s2*2+{x,y} = s_old
//   s_old 0..5: e-weights (r lo, r hi, z lo, z hi, n lo, n hi); 6..11: h-weights.
//   K-pair j = kq*8 + jj -> (j, j+32).
#define DF_W   0         // 12288 ull = 24576 f
#define DF_CST 24576     // 192
#define DF_RES 24768     // 192
#define DF_OM  24960     // 192
#define DF_BHH 25152     // 192
#define SMEM_DF_BYTES (25344 * 4)

__global__ __launch_bounds__(128, 3)
void kDF(const float* __restrict__ wih_f, const float* __restrict__ whh_f,
         const float* __restrict__ bhh_f,
         const float* __restrict__ wih_r, const float* __restrict__ whh_r,
         const float* __restrict__ bhh_r,
         const float* __restrict__ h_prev, const float* __restrict__ theta,
         float* __restrict__ out) {
    extern __shared__ float smem[];
    const int tid = threadIdx.x, lane = tid & 31, wrp = tid >> 5;
    const int dir = blockIdx.x & 1, u = blockIdx.x >> 1;
    const int kq = lane >> 3, ln = lane & 7;

    ull* wEH = (ull*)(smem + DF_W);
    float* scst = smem + DF_CST;
    float* sres = smem + DF_RES;
    float* som  = smem + DF_OM;
    float* sbhh = smem + DF_BHH;

    const float* wih = dir ? wih_r : wih_f;
    const float* whh = dir ? whh_r : whh_f;
    const float* bhh = dir ? bhh_r : bhh_f;

    for (int idx = tid; idx < 12288; idx += 128) {
        int lohi = idx & 1;
        int iu2 = idx >> 1;
        int s2 = iu2 % 6;
        int t = iu2 / 6;
        int kq2 = t & 3, jj = (t >> 2) & 7, d = t >> 5;
        int s_old = s2 * 2 + lohi;
        int j = kq2 * 8 + jj;
        ull val;
        if (s_old < 6) {
            int g = s_old;
            int o = (g >> 1) * 64 + (g & 1) * 32 + d;
            val = pack2(wih[o * 130 + 64 + j], wih[o * 130 + 96 + j]);
        } else {
            int g = s_old - 6;
            int o = (g >> 1) * 64 + (g & 1) * 32 + d;
            val = pack2(whh[o * 64 + j], whh[o * 64 + 32 + j]);
        }
        wEH[idx] = val;
    }
    for (int i = tid; i < 192; i += 128) {
        scst[i] = dir ? g_const_r[i] : g_const_f[i];
        sres[i] = wih[i * 130 + 128];
        som[i]  = wih[i * 130 + 129];
        sbhh[i] = bhh[i];
    }
    __syncthreads();

    const float* hpd = h_prev + (size_t)dir * B_N * 64;
    const float* out_e = out + (size_t)3 * B_N * 64;
    const float* out_rs = out + (size_t)4 * B_N * 64;
    const float* out_om = out_rs + B_N;
    float* out_t = out;
    float* out_h = out + (size_t)(1 + dir) * B_N * 64;

    const int r0 = u * 64 + wrp * 16 + ln;
    const int r1 = r0 + 8;
    const size_t ro0 = (size_t)r0 * 64, ro1 = (size_t)r1 * 64;

    ull e0_p[8], h0_p[8], e1_p[8], h1_p[8];
    load_quarter_pairs(out_e + ro0, kq, e0_p);
    load_quarter_pairs(hpd + ro0, kq, h0_p);
    load_quarter_pairs(out_e + ro1, kq, e1_p);
    load_quarter_pairs(hpd + ro1, kq, h1_p);
    const float res0 = out_rs[r0], om0 = out_om[r0];
    const float res1 = out_rs[r1], om1 = out_om[r1];

    // epilogue role: (row, half) from kq
    const int rowq = kq & 1, half = kq >> 1;
    const int hb = half << 5;
    const size_t ros = rowq ? ro1 : ro0;
    const float resv = rowq ? res1 : res0;
    const float omv  = rowq ? om1 : om0;

#pragma unroll 1
    for (int d = 0; d < 32; d++) {
        const ulonglong2* w = (const ulonglong2*)wEH + ((d * 8) * 4 + kq) * 6;
        ull A0 = 0, A1 = 0, A2 = 0, A3 = 0, A4 = 0, A5 = 0;
        ull B0 = 0, B1 = 0, B2 = 0, B3 = 0, B4 = 0, B5 = 0;
        ull C0 = 0, C1 = 0, C2 = 0, C3 = 0, C4 = 0, C5 = 0;
        ull D0 = 0, D1 = 0, D2 = 0, D3 = 0, D4 = 0, D5 = 0;
#pragma unroll
        for (int jj = 0; jj < 8; jj++) {
            ulonglong2 q0 = w[0], q1 = w[1], q2 = w[2];
            ulonglong2 q3 = w[3], q4 = w[4], q5 = w[5];
            w += 24;
            ull e0 = e0_p[jj], h0 = h0_p[jj];
            ull e1 = e1_p[jj], h1 = h1_p[jj];
            fma2(A0, q0.x, e0); fma2(A1, q0.y, e0);
            fma2(A2, q1.x, e0); fma2(A3, q1.y, e0);
            fma2(A4, q2.x, e0); fma2(A5, q2.y, e0);
            fma2(B0, q3.x, h0); fma2(B1, q3.y, h0);
            fma2(B2, q4.x, h0); fma2(B3, q4.y, h0);
            fma2(B4, q5.x, h0); fma2(B5, q5.y, h0);
            fma2(C0, q0.x, e1); fma2(C1, q0.y, e1);
            fma2(C2, q1.x, e1); fma2(C3, q1.y, e1);
            fma2(C4, q2.x, e1); fma2(C5, q2.y, e1);
            fma2(D0, q3.x, h1); fma2(D1, q3.y, h1);
            fma2(D2, q4.x, h1); fma2(D3, q4.y, h1);
            fma2(D4, q5.x, h1); fma2(D5, q5.y, h1);
        }
#define COMB(x) ({ float _f = hadd2(x); \
        _f += __shfl_xor_sync(0xffffffffu, _f, 8); \
        _f += __shfl_xor_sync(0xffffffffu, _f, 16); _f; })
        float a0 = COMB(A0), a1 = COMB(A1), a2 = COMB(A2);
        float a3 = COMB(A3), a4 = COMB(A4), a5 = COMB(A5);
        float b0 = COMB(B0), b1 = COMB(B1), b2 = COMB(B2);
        float b3 = COMB(B3), b4 = COMB(B4), b5 = COMB(B5);
        float c0 = COMB(C0), c1 = COMB(C1), c2 = COMB(C2);
        float c3 = COMB(C3), c4 = COMB(C4), c5 = COMB(C5);
        float d0 = COMB(D0), d1 = COMB(D1), d2 = COMB(D2);
        float d3 = COMB(D3), d4 = COMB(D4), d5 = COMB(D5);
#undef COMB

        float sr = half ? (rowq ? c1 : a1) : (rowq ? c0 : a0);
        float sz = half ? (rowq ? c3 : a3) : (rowq ? c2 : a2);
        float sn = half ? (rowq ? c5 : a5) : (rowq ? c4 : a4);
        float tr = half ? (rowq ? d1 : b1) : (rowq ? d0 : b0);
        float tz = half ? (rowq ? d3 : b3) : (rowq ? d2 : b2);
        float tn = half ? (rowq ? d5 : b5) : (rowq ? d4 : b4);

        const int i_r = hb + d, i_z = 64 + hb + d, i_n = 128 + hb + d;
        float ir  = sr + scst[i_r] + resv * sres[i_r] + omv * som[i_r];
        float iz  = sz + scst[i_z] + resv * sres[i_z] + omv * som[i_z];
        float inx = sn + scst[i_n] + resv * sres[i_n] + omv * som[i_n];
        float hr = tr + sbhh[i_r];
        float hz = tz + sbhh[i_z];
        float hn = tn + sbhh[i_n];
        float hv = hpd[ros + hb + d];
        float rg = sigm(ir + hr), zg = sigm(iz + hz);
        float ng = ftanh(inx + rg * hn);
        float o = (1.f - zg) * ng + zg * hv;
        out_h[ros + hb + d] = o;
        if (dir == 0) {
            out_t[ros + hb + d] = 0.3f * theta[ros + hb + d] + 0.7f * o;
        }
    }
}

extern "C" void kernel_launch(void* const* d_in, const int* in_sizes, int n_in,
                              void* d_out, int out_size) {
    const float* theta   = (const float*)d_in[0];
    const float* context = (const float*)d_in[1];
    const float* h_prev  = (const float*)d_in[2];
    const float* memory  = (const float*)d_in[3];
    const float* tw      = (const float*)d_in[4];
    const float* ipw     = (const float*)d_in[5];
    const float* ipb     = (const float*)d_in[6];
    const float* ow      = (const float*)d_in[7];
    const float* ob      = (const float*)d_in[8];
    const float* emo_w1  = (const float*)d_in[9];
    const float* emo_b1  = (const float*)d_in[10];
    const float* emo_w2  = (const float*)d_in[11];
    const float* emo_b2  = (const float*)d_in[12];
    const float* pe      = (const float*)d_in[13];
    const float* ctx_w   = (const float*)d_in[14];
    const float* ctx_b   = (const float*)d_in[15];
    const float* ideal_w = (const float*)d_in[16];
    const float* ideal_b = (const float*)d_in[17];
    const float* wih_f   = (const float*)d_in[18];
    const float* whh_f   = (const float*)d_in[19];
    const float* bih_f   = (const float*)d_in[20];
    const float* bhh_f   = (const float*)d_in[21];
    const float* wih_r   = (const float*)d_in[22];
    const float* whh_r   = (const float*)d_in[23];
    const float* bih_r   = (const float*)d_in[24];
    const float* bhh_r   = (const float*)d_in[25];
    const float* freq_w  = (const float*)d_in[26];
    const float* freq_b  = (const float*)d_in[27];
    const float* prev_i  = (const float*)d_in[28];
    float* out = (float*)d_out;

    static bool attr_set = false;
    if (!attr_set) {
        cudaFuncSetAttribute(kB1, cudaFuncAttributeMaxDynamicSharedMemorySize, SMEM_B1_BYTES);
        cudaFuncSetAttribute(kB2a, cudaFuncAttributeMaxDynamicSharedMemorySize, SMEM_B2A_BYTES);
        cudaFuncSetAttribute(kDF, cudaFuncAttributeMaxDynamicSharedMemorySize, SMEM_DF_BYTES);
        attr_set = true;
    }

    kA<<<1, 192>>>(memory, tw, ipw, ipb, ow, ob, wih_f, bih_f, wih_r, bih_r);
    kM<<<15, 128>>>(ideal_w, ideal_b, ctx_w, ctx_b);
    kB1<<<296, 128, SMEM_B1_BYTES>>>(theta, context, ideal_w,
                                     pe, prev_i, freq_w, freq_b, out);
    kB2a<<<444, 128, SMEM_B2A_BYTES>>>(theta, emo_w1, emo_b1, emo_w2, emo_b2, out);
    kDF<<<2048, 128, SMEM_DF_BYTES>>>(wih_f, whh_f, bhh_f, wih_r, whh_r, bhh_r,
                                      h_prev, theta, out);
}

// round 15
// speedup vs baseline: 1.0102x; 1.0102x over previous
#include <cuda_runtime.h>
#include <cstdint>

#define B_N   65536
#define CTXD  384
#define NPR   5
#define MEMV  10
#define EPSV  1e-8f
#define NPART 296

typedef unsigned long long ull;

__device__ float g_part[NPART];
__device__ float g_const_f[192];
__device__ float g_const_r[192];
__device__ float g_M[NPR * CTXD];
__device__ float g_lb[NPR];

__device__ __forceinline__ ull pack2(float lo, float hi) {
    ull r; asm("mov.b64 %0,{%1,%2};" : "=l"(r) : "f"(lo), "f"(hi)); return r;
}
__device__ __forceinline__ float2 unpack2(ull v) {
    float2 f; asm("mov.b64 {%0,%1},%2;" : "=f"(f.x), "=f"(f.y) : "l"(v)); return f;
}
__device__ __forceinline__ void fma2(ull& acc, ull a, ull b) {
    asm("fma.rn.f32x2 %0,%1,%2,%0;" : "+l"(acc) : "l"(a), "l"(b));
}
__device__ __forceinline__ float hadd2(ull v) { float2 f = unpack2(v); return f.x + f.y; }
__device__ __forceinline__ float wsum(float v) {
#pragma unroll
    for (int o = 16; o; o >>= 1) v += __shfl_xor_sync(0xffffffffu, v, o);
    return v;
}
__device__ __forceinline__ float sigm(float x) { return __fdividef(1.0f, 1.0f + __expf(-x)); }
__device__ __forceinline__ float ftanh(float x) { return 1.0f - __fdividef(2.0f, 1.0f + __expf(2.0f * x)); }

__device__ __forceinline__ void load_row_pairs(const float* p, ull* dst) {
    const float4* v = (const float4*)p;
#pragma unroll
    for (int k = 0; k < 8; k++) {
        float4 a = v[k], b = v[k + 8];
        dst[k * 4 + 0] = pack2(a.x, b.x);
        dst[k * 4 + 1] = pack2(a.y, b.y);
        dst[k * 4 + 2] = pack2(a.z, b.z);
        dst[k * 4 + 3] = pack2(a.w, b.w);
    }
}

__device__ __forceinline__ void load_half_pairs(const float* p, int kh, ull* dst) {
    const float4* v = (const float4*)p;
#pragma unroll
    for (int q = 0; q < 4; q++) {
        float4 a = v[kh * 4 + q], b = v[kh * 4 + 8 + q];
        dst[q * 4 + 0] = pack2(a.x, b.x);
        dst[q * 4 + 1] = pack2(a.y, b.y);
        dst[q * 4 + 2] = pack2(a.z, b.z);
        dst[q * 4 + 3] = pack2(a.w, b.w);
    }
}

// ---------------- kA: batch-constant MHA branch + GRU constant fold ----------------
__global__ void kA(const float* __restrict__ memory, const float* __restrict__ tw,
                   const float* __restrict__ ipw, const float* __restrict__ ipb,
                   const float* __restrict__ ow, const float* __restrict__ ob,
                   const float* __restrict__ wih_f, const float* __restrict__ bih_f,
                   const float* __restrict__ wih_r, const float* __restrict__ bih_r) {
    __shared__ float mt[64], vv[64], ov[64];
    int t = threadIdx.x;  // 192 threads
    if (t < 64) {
        float a[MEMV], m = -1e30f, s = 0.f;
#pragma unroll
        for (int i = 0; i < MEMV; i++) { a[i] = tw[i]; m = fmaxf(m, a[i]); }
#pragma unroll
        for (int i = 0; i < MEMV; i++) { a[i] = __expf(a[i] - m); s += a[i]; }
        float inv = 1.f / s, acc = 0.f;
#pragma unroll
        for (int i = 0; i < MEMV; i++) acc += (a[i] * inv) * memory[i * 64 + t];
        mt[t] = acc;
    }
    __syncthreads();
    if (t < 64) {
        float v = ipb[128 + t];
        for (int j = 0; j < 64; j++) v += mt[j] * ipw[(128 + t) * 64 + j];
        vv[t] = v;
    }
    __syncthreads();
    if (t < 64) {
        float o = ob[t];
        for (int j = 0; j < 64; j++) o += vv[j] * ow[t * 64 + j];
        ov[t] = o;
    }
    __syncthreads();
    float af = bih_f[t], ar = bih_r[t];
    for (int j = 0; j < 64; j++) {
        float o = ov[j];
        af += wih_f[t * 130 + j] * o;
        ar += wih_r[t * 130 + j] * o;
    }
    g_const_f[t] = af;
    g_const_r[t] = ar;
}

// ---------------- kM: fold ctx GEMM into logit matrix M = idw_c @ ctx_w ----------------
__global__ void kM(const float* __restrict__ ideal_w, const float* __restrict__ ideal_b,
                   const float* __restrict__ ctx_w, const float* __restrict__ ctx_b) {
    int idx = blockIdx.x * 128 + threadIdx.x;
    if (idx < NPR * CTXD) {
        int p = idx / CTXD, k = idx - p * CTXD;
        float s = 0.f;
        for (int d = 0; d < 64; d++)
            s += ideal_w[p * 128 + 64 + d] * ctx_w[d * CTXD + k];
        g_M[idx] = s;
    }
    if (idx < NPR) {
        float s = ideal_b[idx];
        for (int d = 0; d < 64; d++)
            s += ideal_w[idx * 128 + 64 + d] * ctx_b[d];
        g_lb[idx] = s;
    }
}

// ---------------- kB1: prime logits (via M) + softmax + scalars (2 rows/lane) ----------------
#define B1_M    0        // 1920 f
#define B1_IDWT 1920     // 160 ull = 320 f
#define B1_PE   2240     // 160 ull
#define B1_PREV 2560     // 32 ull
#define B1_LB   2624     // 8
#define B1_PART 2632     // 4
#define SMEM_B1_BYTES (2640 * 4)

__global__ __launch_bounds__(128, 2)
void kB1(const float* __restrict__ theta, const float* __restrict__ context,
         const float* __restrict__ ideal_w,
         const float* __restrict__ prime_embeds, const float* __restrict__ prev_ideal,
         const float* __restrict__ freq_w, const float* __restrict__ freq_b,
         float* __restrict__ out) {
    extern __shared__ float smem[];
    const int tid = threadIdx.x, lane = tid & 31, wrp = tid >> 5;

    float* Ms = smem + B1_M;
    ull* idwt = (ull*)(smem + B1_IDWT);
    ull* pe_s = (ull*)(smem + B1_PE);
    ull* prev_s = (ull*)(smem + B1_PREV);
    float* s_lb = smem + B1_LB;
    float* s_part = smem + B1_PART;

    for (int idx = tid; idx < NPR * CTXD; idx += 128) Ms[idx] = g_M[idx];
    for (int idx = tid; idx < 160; idx += 128) {
        int p = idx >> 5, j = idx & 31;
        idwt[idx] = pack2(ideal_w[p * 128 + j], ideal_w[p * 128 + j + 32]);
        pe_s[idx] = pack2(prime_embeds[p * 64 + j], prime_embeds[p * 64 + j + 32]);
    }
    if (tid < 32) prev_s[tid] = pack2(prev_ideal[tid], prev_ideal[tid + 32]);
    if (tid < NPR) s_lb[tid] = g_lb[tid];
    __syncthreads();

    const float fwv = freq_w[0], fbv = freq_b[0];
    float* out_rs = out + (size_t)4 * B_N * 64;
    float* out_om = out_rs + B_N;
    float* out_pw = out_om + B_N;

    const int u = blockIdx.x * 4 + wrp;
    float stress_total = 0.f;
    if (u < 1024) {
        const int r0 = u * 64 + lane, r1 = r0 + 32;

        float lg0[NPR], lg1[NPR];
#pragma unroll
        for (int p = 0; p < NPR; p++) { lg0[p] = s_lb[p]; lg1[p] = s_lb[p]; }
        const float4* x0v = (const float4*)(context + (size_t)r0 * CTXD);
        const float4* x1v = (const float4*)(context + (size_t)r1 * CTXD);
#pragma unroll 4
        for (int k4 = 0; k4 < 96; k4++) {
            float4 a0 = x0v[k4], a1 = x1v[k4];
#pragma unroll
            for (int p = 0; p < NPR; p++) {
                float4 m = ((const float4*)(Ms + p * CTXD))[k4];
                lg0[p] += m.x * a0.x + m.y * a0.y + m.z * a0.z + m.w * a0.w;
                lg1[p] += m.x * a1.x + m.y * a1.y + m.z * a1.z + m.w * a1.w;
            }
        }

        ull th0[32], th1[32];
        load_row_pairs(theta + (size_t)r0 * 64, th0);
        load_row_pairs(theta + (size_t)r1 * 64, th1);
#pragma unroll
        for (int p5 = 0; p5 < NPR; p5++) {
            ull a = 0, b = 0;
#pragma unroll
            for (int j = 0; j < 32; j++) {
                ull w = idwt[p5 * 32 + j];
                fma2(a, w, th0[j]);
                fma2(b, w, th1[j]);
            }
            lg0[p5] += hadd2(a);
            lg1[p5] += hadd2(b);
        }

        float pw0[NPR], pw1[NPR];
        {
            float m0 = lg0[0], m1 = lg1[0];
#pragma unroll
            for (int p = 1; p < NPR; p++) { m0 = fmaxf(m0, lg0[p]); m1 = fmaxf(m1, lg1[p]); }
            float s0 = 0.f, s1 = 0.f;
#pragma unroll
            for (int p = 0; p < NPR; p++) {
                pw0[p] = __expf(lg0[p] - m0); s0 += pw0[p];
                pw1[p] = __expf(lg1[p] - m1); s1 += pw1[p];
            }
            float i0 = __fdividef(1.f, s0), i1 = __fdividef(1.f, s1);
#pragma unroll
            for (int p = 0; p < NPR; p++) {
                pw0[p] *= i0; pw1[p] *= i1;
                out_pw[(size_t)r0 * NPR + p] = pw0[p];
                out_pw[(size_t)r1 * NPR + p] = pw1[p];
            }
        }

        float str0 = 0.f, nth0 = 0.f, nti0 = 0.f, rd0 = 0.f, f20 = 0.f;
        float str1 = 0.f, nth1 = 0.f, nti1 = 0.f, rd1 = 0.f, f21 = 0.f;
#pragma unroll
        for (int j = 0; j < 32; j++) {
            float2 pv = unpack2(prev_s[j]);
            float2 pe0 = unpack2(pe_s[0 * 32 + j]);
            float2 pe1 = unpack2(pe_s[1 * 32 + j]);
            float2 pe2 = unpack2(pe_s[2 * 32 + j]);
            float2 pe3 = unpack2(pe_s[3 * 32 + j]);
            float2 pe4 = unpack2(pe_s[4 * 32 + j]);
            {
                float tix = pw0[0] * pe0.x + pw0[1] * pe1.x + pw0[2] * pe2.x
                          + pw0[3] * pe3.x + pw0[4] * pe4.x;
                float tiy = pw0[0] * pe0.y + pw0[1] * pe1.y + pw0[2] * pe2.y
                          + pw0[3] * pe3.y + pw0[4] * pe4.y;
                float2 t = unpack2(th0[j]);
                float dx = t.x - tix, dy = t.y - tiy;
                str0 += dx * dx + dy * dy;
                nth0 += t.x * t.x + t.y * t.y;
                nti0 += tix * tix + tiy * tiy;
                rd0  += t.x * tix + t.y * tiy;
                float px = tix - pv.x, py = tiy - pv.y;
                f20 += px * px + py * py;
            }
            {
                float tix = pw1[0] * pe0.x + pw1[1] * pe1.x + pw1[2] * pe2.x
                          + pw1[3] * pe3.x + pw1[4] * pe4.x;
                float tiy = pw1[0] * pe0.y + pw1[1] * pe1.y + pw1[2] * pe2.y
                          + pw1[3] * pe3.y + pw1[4] * pe4.y;
                float2 t = unpack2(th1[j]);
                float dx = t.x - tix, dy = t.y - tiy;
                str1 += dx * dx + dy * dy;
                nth1 += t.x * t.x + t.y * t.y;
                nti1 += tix * tix + tiy * tiy;
                rd1  += t.x * tix + t.y * tiy;
                float px = tix - pv.x, py = tiy - pv.y;
                f21 += px * px + py * py;
            }
        }
        {
            float it0 = __fdividef(1.f, sqrtf(nth0) + EPSV);
            float ii0 = __fdividef(1.f, sqrtf(nti0) + EPSV);
            out_rs[r0] = __fdividef(rd0 * it0 * ii0,
                                    fmaxf(sqrtf(nth0) * it0 * sqrtf(nti0) * ii0, EPSV));
            float fr0 = sqrtf(f20);
            out_om[r0] = ftanh(fr0 * fwv + fbv) * (1.0f + 0.1f * __sinf(fr0));
            float it1 = __fdividef(1.f, sqrtf(nth1) + EPSV);
            float ii1 = __fdividef(1.f, sqrtf(nti1) + EPSV);
            out_rs[r1] = __fdividef(rd1 * it1 * ii1,
                                    fmaxf(sqrtf(nth1) * it1 * sqrtf(nti1) * ii1, EPSV));
            float fr1 = sqrtf(f21);
            out_om[r1] = ftanh(fr1 * fwv + fbv) * (1.0f + 0.1f * __sinf(fr1));
        }
        stress_total = str0 + str1;
    }

    float ws = wsum(stress_total);
    if (lane == 0) s_part[wrp] = ws;
    __syncthreads();
    if (tid == 0) {
        g_part[blockIdx.x] = (s_part[0] + s_part[1]) + (s_part[2] + s_part[3]);
    }
}

// ---------------- kB2a: emotion MLP -> out_e = relu(..) + 0.001*stress ----------------
#define B2A_W1  0        // 4096 ull
#define B2A_W2  8192     // 4096 ull
#define B2A_B1  16384    // 128
#define B2A_B2  16512    // 64
#define B2A_STC 16576    // 1
#define SMEM_B2A_BYTES (16580 * 4)

__global__ __launch_bounds__(128, 3)
void kB2a(const float* __restrict__ theta,
          const float* __restrict__ emo_w1, const float* __restrict__ emo_b1,
          const float* __restrict__ emo_w2, const float* __restrict__ emo_b2,
          float* __restrict__ out) {
    extern __shared__ float smem[];
    const int tid = threadIdx.x, lane = tid & 31, wrp = tid >> 5;
    ull* w1i = (ull*)(smem + B2A_W1);
    ull* w2i = (ull*)(smem + B2A_W2);
    float* s_b1 = smem + B2A_B1;
    float* s_b2 = smem + B2A_B2;
    float* s_stc = smem + B2A_STC;

    for (int idx = tid; idx < 4096; idx += 128) {
        int oi = idx & 7, j = (idx >> 3) & 31, og = idx >> 8;
        int o = og * 8 + oi;
        w1i[idx] = pack2(emo_w1[o * 64 + j], emo_w1[o * 64 + j + 32]);
    }
    for (int idx = tid; idx < 4096; idx += 128) {
        int di = idx & 31, kh = idx >> 5;
        w2i[idx] = pack2(emo_w2[di * 128 + kh], emo_w2[(di + 32) * 128 + kh]);
    }
    if (tid < 128) s_b1[tid] = emo_b1[tid];
    if (tid < 64) s_b2[tid] = emo_b2[tid];
    if (tid == 0) {
        float s = 0.f;
        for (int b = 0; b < NPART; b++) s += g_part[b];
        s_stc[0] = 0.001f * s;
    }
    __syncthreads();
    const float stc = s_stc[0];

    float* out_e = out + (size_t)3 * B_N * 64;

#pragma unroll 1
    for (int u = blockIdx.x * 4 + wrp; u < 2048; u += 444 * 4) {
        const int r = u * 32 + lane;
        const size_t ro = (size_t)r * 64;

        ull th_p[32];
        load_row_pairs(theta + ro, th_p);

        ull e_acc[32];
#pragma unroll
        for (int di = 0; di < 32; di++) e_acc[di] = pack2(s_b2[di], s_b2[di + 32]);
        const ulonglong2* w1v = (const ulonglong2*)w1i;
        const ulonglong2* w2v = (const ulonglong2*)w2i;
#pragma unroll 1
        for (int og = 0; og < 16; og++) {
            ull a0 = 0, a1 = 0, a2 = 0, a3 = 0, a4 = 0, a5 = 0, a6 = 0, a7 = 0;
#pragma unroll
            for (int j = 0; j < 32; j++) {
                ulonglong2 p0 = w1v[0], p1 = w1v[1];
                ulonglong2 p2 = w1v[2], p3 = w1v[3];
                w1v += 4;
                ull t = th_p[j];
                fma2(a0, p0.x, t); fma2(a1, p0.y, t);
                fma2(a2, p1.x, t); fma2(a3, p1.y, t);
                fma2(a4, p2.x, t); fma2(a5, p2.y, t);
                fma2(a6, p3.x, t); fma2(a7, p3.y, t);
            }
            float t8[8];
            t8[0] = ftanh(hadd2(a0) + s_b1[og * 8 + 0]);
            t8[1] = ftanh(hadd2(a1) + s_b1[og * 8 + 1]);
            t8[2] = ftanh(hadd2(a2) + s_b1[og * 8 + 2]);
            t8[3] = ftanh(hadd2(a3) + s_b1[og * 8 + 3]);
            t8[4] = ftanh(hadd2(a4) + s_b1[og * 8 + 4]);
            t8[5] = ftanh(hadd2(a5) + s_b1[og * 8 + 5]);
            t8[6] = ftanh(hadd2(a6) + s_b1[og * 8 + 6]);
            t8[7] = ftanh(hadd2(a7) + s_b1[og * 8 + 7]);
#pragma unroll
            for (int k = 0; k < 8; k++) {
                ull tt = pack2(t8[k], t8[k]);
#pragma unroll
                for (int di2 = 0; di2 < 16; di2++) {
                    ulonglong2 q = w2v[di2];
                    fma2(e_acc[di2 * 2 + 0], q.x, tt);
                    fma2(e_acc[di2 * 2 + 1], q.y, tt);
                }
                w2v += 16;
            }
        }
        float4* ep = (float4*)(out_e + ro);
#pragma unroll
        for (int k = 0; k < 8; k++) {
            float2 v0 = unpack2(e_acc[k * 4 + 0]);
            float2 v1 = unpack2(e_acc[k * 4 + 1]);
            float2 v2 = unpack2(e_acc[k * 4 + 2]);
            float2 v3 = unpack2(e_acc[k * 4 + 3]);
            ep[k]     = make_float4(fmaxf(v0.x, 0.f) + stc, fmaxf(v1.x, 0.f) + stc,
                                    fmaxf(v2.x, 0.f) + stc, fmaxf(v3.x, 0.f) + stc);
            ep[8 + k] = make_float4(fmaxf(v0.y, 0.f) + stc, fmaxf(v1.y, 0.f) + stc,
                                    fmaxf(v2.y, 0.f) + stc, fmaxf(v3.y, 0.f) + stc);
        }
    }
}

// ---------------- kDF: fused GRU, half-warp K-split, split epilogue ----------------
#define DF_W   0         // 12288 ull = 24576 f
#define DF_CST 24576     // 192
#define DF_RES 24768     // 192
#define DF_OM  24960     // 192
#define DF_BHH 25152     // 192
#define SMEM_DF_BYTES (25344 * 4)

__global__ __launch_bounds__(256, 2)
void kDF(const float* __restrict__ wih_f, const float* __restrict__ whh_f,
         const float* __restrict__ bhh_f,
         const float* __restrict__ wih_r, const float* __restrict__ whh_r,
         const float* __restrict__ bhh_r,
         const float* __restrict__ h_prev, const float* __restrict__ theta,
         float* __restrict__ out) {
    extern __shared__ float smem[];
    const int tid = threadIdx.x, lane = tid & 31, wrp = tid >> 5;
    const int dir = blockIdx.x & 1, ublk = blockIdx.x >> 1;
    const int kh = lane >> 4, ln = lane & 15;

    ull* wEH = (ull*)(smem + DF_W);
    float* scst = smem + DF_CST;
    float* sres = smem + DF_RES;
    float* som  = smem + DF_OM;
    float* sbhh = smem + DF_BHH;

    const float* wih = dir ? wih_r : wih_f;
    const float* whh = dir ? whh_r : whh_f;
    const float* bhh = dir ? bhh_r : bhh_f;

    for (int idx = tid; idx < 12288; idx += 256) {
        int s = idx % 12, t = idx / 12;
        int j = t & 31, d = t >> 5;
        int g = (s >= 6) ? s - 6 : s;
        int o = (g >> 1) * 64 + (g & 1) * 32 + d;
        wEH[idx] = (s < 6) ? pack2(wih[o * 130 + 64 + j], wih[o * 130 + 96 + j])
                           : pack2(whh[o * 64 + j], whh[o * 64 + 32 + j]);
    }
    for (int i = tid; i < 192; i += 256) {
        scst[i] = dir ? g_const_r[i] : g_const_f[i];
        sres[i] = wih[i * 130 + 128];
        som[i]  = wih[i * 130 + 129];
        sbhh[i] = bhh[i];
    }
    __syncthreads();

    const float* hpd = h_prev + (size_t)dir * B_N * 64;
    const float* out_e = out + (size_t)3 * B_N * 64;
    const float* out_rs = out + (size_t)4 * B_N * 64;
    const float* out_om = out_rs + B_N;
    float* out_t = out;
    float* out_h = out + (size_t)(1 + dir) * B_N * 64;

#pragma unroll 1
    for (int u = ublk; u < 512; u += 296) {
        const int r = u * 128 + wrp * 16 + ln;
        const size_t ro = (size_t)r * 64;

        ull e_p[16], h_p[16];
        load_half_pairs(out_e + ro, kh, e_p);
        load_half_pairs(hpd + ro, kh, h_p);
        const float res = out_rs[r], om = out_om[r];

        const ulonglong2* wbase = (const ulonglong2*)(wEH + (size_t)(kh * 16) * 12);
#pragma unroll 1
        for (int d = 0; d < 32; d++) {
            const ulonglong2* w = wbase + (size_t)d * 192;
            ull A0 = 0, A1 = 0, A2 = 0, A3 = 0, A4 = 0, A5 = 0;
            ull B0 = 0, B1 = 0, B2 = 0, B3 = 0, B4 = 0, B5 = 0;
#pragma unroll
            for (int jj = 0; jj < 16; jj++) {
                ulonglong2 q0 = w[0], q1 = w[1], q2 = w[2];
                ulonglong2 q3 = w[3], q4 = w[4], q5 = w[5];
                w += 6;
                ull e = e_p[jj], h = h_p[jj];
                fma2(A0, q0.x, e); fma2(A1, q0.y, e);
                fma2(A2, q1.x, e); fma2(A3, q1.y, e);
                fma2(A4, q2.x, e); fma2(A5, q2.y, e);
                fma2(B0, q3.x, h); fma2(B1, q3.y, h);
                fma2(B2, q4.x, h); fma2(B3, q4.y, h);
                fma2(B4, q5.x, h); fma2(B5, q5.y, h);
            }
            float a0 = hadd2(A0); a0 += __shfl_xor_sync(0xffffffffu, a0, 16);
            float a1 = hadd2(A1); a1 += __shfl_xor_sync(0xffffffffu, a1, 16);
            float a2 = hadd2(A2); a2 += __shfl_xor_sync(0xffffffffu, a2, 16);
            float a3 = hadd2(A3); a3 += __shfl_xor_sync(0xffffffffu, a3, 16);
            float a4 = hadd2(A4); a4 += __shfl_xor_sync(0xffffffffu, a4, 16);
            float a5 = hadd2(A5); a5 += __shfl_xor_sync(0xffffffffu, a5, 16);
            float b0 = hadd2(B0); b0 += __shfl_xor_sync(0xffffffffu, b0, 16);
            float b1 = hadd2(B1); b1 += __shfl_xor_sync(0xffffffffu, b1, 16);
            float b2 = hadd2(B2); b2 += __shfl_xor_sync(0xffffffffu, b2, 16);
            float b3 = hadd2(B3); b3 += __shfl_xor_sync(0xffffffffu, b3, 16);
            float b4 = hadd2(B4); b4 += __shfl_xor_sync(0xffffffffu, b4, 16);
            float b5 = hadd2(B5); b5 += __shfl_xor_sync(0xffffffffu, b5, 16);

            // split epilogue: kh=0 -> output d (lo), kh=1 -> output d+32 (hi)
            const int hb = kh << 5;
            float sa_r = kh ? a1 : a0;
            float sa_z = kh ? a3 : a2;
            float sa_n = kh ? a5 : a4;
            float sb_r = kh ? b1 : b0;
            float sb_z = kh ? b3 : b2;
            float sb_n = kh ? b5 : b4;
            const int i_r = hb + d, i_z = 64 + hb + d, i_n = 128 + hb + d;
            float ir  = sa_r + scst[i_r] + res * sres[i_r] + om * som[i_r];
            float iz  = sa_z + scst[i_z] + res * sres[i_z] + om * som[i_z];
            float inx = sa_n + scst[i_n] + res * sres[i_n] + om * som[i_n];
            float hr = sb_r + sbhh[i_r];
            float hz = sb_z + sbhh[i_z];
            float hn = sb_n + sbhh[i_n];
            float hv = hpd[ro + hb + d];
            float rg = sigm(ir + hr), zg = sigm(iz + hz);
            float ng = ftanh(inx + rg * hn);
            float o = (1.f - zg) * ng + zg * hv;
            out_h[ro + hb + d] = o;
            if (dir == 0) {
                out_t[ro + hb + d] = 0.3f * theta[ro + hb + d] + 0.7f * o;
            }
        }
    }
}

extern "C" void kernel_launch(void* const* d_in, const int* in_sizes, int n_in,
                              void* d_out, int out_size) {
    const float* theta   = (const float*)d_in[0];
    const float* context = (const float*)d_in[1];
    const float* h_prev  = (const float*)d_in[2];
    const float* memory  = (const float*)d_in[3];
    const float* tw      = (const float*)d_in[4];
    const float* ipw     = (const float*)d_in[5];
    const float* ipb     = (const float*)d_in[6];
    const float* ow      = (const float*)d_in[7];
    const float* ob      = (const float*)d_in[8];
    const float* emo_w1  = (const float*)d_in[9];
    const float* emo_b1  = (const float*)d_in[10];
    const float* emo_w2  = (const float*)d_in[11];
    const float* emo_b2  = (const float*)d_in[12];
    const float* pe      = (const float*)d_in[13];
    const float* ctx_w   = (const float*)d_in[14];
    const float* ctx_b   = (const float*)d_in[15];
    const float* ideal_w = (const float*)d_in[16];
    const float* ideal_b = (const float*)d_in[17];
    const float* wih_f   = (const float*)d_in[18];
    const float* whh_f   = (const float*)d_in[19];
    const float* bih_f   = (const float*)d_in[20];
    const float* bhh_f   = (const float*)d_in[21];
    const float* wih_r   = (const float*)d_in[22];
    const float* whh_r   = (const float*)d_in[23];
    const float* bih_r   = (const float*)d_in[24];
    const float* bhh_r   = (const float*)d_in[25];
    const float* freq_w  = (const float*)d_in[26];
    const float* freq_b  = (const float*)d_in[27];
    const float* prev_i  = (const float*)d_in[28];
    float* out = (float*)d_out;

    static bool attr_set = false;
    if (!attr_set) {
        cudaFuncSetAttribute(kB1, cudaFuncAttributeMaxDynamicSharedMemorySize, SMEM_B1_BYTES);
        cudaFuncSetAttribute(kB2a, cudaFuncAttributeMaxDynamicSharedMemorySize, SMEM_B2A_BYTES);
        cudaFuncSetAttribute(kDF, cudaFuncAttributeMaxDynamicSharedMemorySize, SMEM_DF_BYTES);
        attr_set = true;
    }

    kA<<<1, 192>>>(memory, tw, ipw, ipb, ow, ob, wih_f, bih_f, wih_r, bih_r);
    kM<<<15, 128>>>(ideal_w, ideal_b, ctx_w, ctx_b);
    kB1<<<296, 128, SMEM_B1_BYTES>>>(theta, context, ideal_w,
                                     pe, prev_i, freq_w, freq_b, out);
    kB2a<<<444, 128, SMEM_B2A_BYTES>>>(theta, emo_w1, emo_b1, emo_w2, emo_b2, out);
    kDF<<<592, 256, SMEM_DF_BYTES>>>(wih_f, whh_f, bhh_f, wih_r, whh_r, bhh_r,
                                     h_prev, theta, out);
}

// round 16
// speedup vs baseline: 1.0620x; 1.0513x over previous
#include <cuda_runtime.h>
#include <cstdint>

#define B_N   65536
#define CTXD  384
#define NPR   5
#define MEMV  10
#define EPSV  1e-8f
#define NPART 296

typedef unsigned long long ull;

__device__ float g_part[NPART];
__device__ float g_const_f[192];
__device__ float g_const_r[192];
__device__ float g_M[NPR * CTXD];
__device__ float g_lb[NPR];

__device__ __forceinline__ ull pack2(float lo, float hi) {
    ull r; asm("mov.b64 %0,{%1,%2};" : "=l"(r) : "f"(lo), "f"(hi)); return r;
}
__device__ __forceinline__ float2 unpack2(ull v) {
    float2 f; asm("mov.b64 {%0,%1},%2;" : "=f"(f.x), "=f"(f.y) : "l"(v)); return f;
}
__device__ __forceinline__ void fma2(ull& acc, ull a, ull b) {
    asm("fma.rn.f32x2 %0,%1,%2,%0;" : "+l"(acc) : "l"(a), "l"(b));
}
__device__ __forceinline__ float hadd2(ull v) { float2 f = unpack2(v); return f.x + f.y; }
__device__ __forceinline__ float wsum(float v) {
#pragma unroll
    for (int o = 16; o; o >>= 1) v += __shfl_xor_sync(0xffffffffu, v, o);
    return v;
}
__device__ __forceinline__ float sigm(float x) { return __fdividef(1.0f, 1.0f + __expf(-x)); }
__device__ __forceinline__ float ftanh(float x) { return 1.0f - __fdividef(2.0f, 1.0f + __expf(2.0f * x)); }

__device__ __forceinline__ void load_row_pairs(const float* p, ull* dst) {
    const float4* v = (const float4*)p;
#pragma unroll
    for (int k = 0; k < 8; k++) {
        float4 a = v[k], b = v[k + 8];
        dst[k * 4 + 0] = pack2(a.x, b.x);
        dst[k * 4 + 1] = pack2(a.y, b.y);
        dst[k * 4 + 2] = pack2(a.z, b.z);
        dst[k * 4 + 3] = pack2(a.w, b.w);
    }
}

// ---------------- kA: batch-constant MHA branch + GRU constant fold ----------------
__global__ void kA(const float* __restrict__ memory, const float* __restrict__ tw,
                   const float* __restrict__ ipw, const float* __restrict__ ipb,
                   const float* __restrict__ ow, const float* __restrict__ ob,
                   const float* __restrict__ wih_f, const float* __restrict__ bih_f,
                   const float* __restrict__ wih_r, const float* __restrict__ bih_r) {
    __shared__ float mt[64], vv[64], ov[64];
    int t = threadIdx.x;  // 192 threads
    if (t < 64) {
        float a[MEMV], m = -1e30f, s = 0.f;
#pragma unroll
        for (int i = 0; i < MEMV; i++) { a[i] = tw[i]; m = fmaxf(m, a[i]); }
#pragma unroll
        for (int i = 0; i < MEMV; i++) { a[i] = __expf(a[i] - m); s += a[i]; }
        float inv = 1.f / s, acc = 0.f;
#pragma unroll
        for (int i = 0; i < MEMV; i++) acc += (a[i] * inv) * memory[i * 64 + t];
        mt[t] = acc;
    }
    __syncthreads();
    if (t < 64) {
        float v = ipb[128 + t];
        for (int j = 0; j < 64; j++) v += mt[j] * ipw[(128 + t) * 64 + j];
        vv[t] = v;
    }
    __syncthreads();
    if (t < 64) {
        float o = ob[t];
        for (int j = 0; j < 64; j++) o += vv[j] * ow[t * 64 + j];
        ov[t] = o;
    }
    __syncthreads();
    float af = bih_f[t], ar = bih_r[t];
    for (int j = 0; j < 64; j++) {
        float o = ov[j];
        af += wih_f[t * 130 + j] * o;
        ar += wih_r[t * 130 + j] * o;
    }
    g_const_f[t] = af;
    g_const_r[t] = ar;
}

// ---------------- kM: fold ctx GEMM into logit matrix M = idw_c @ ctx_w ----------------
__global__ void kM(const float* __restrict__ ideal_w, const float* __restrict__ ideal_b,
                   const float* __restrict__ ctx_w, const float* __restrict__ ctx_b) {
    int idx = blockIdx.x * 128 + threadIdx.x;
    if (idx < NPR * CTXD) {
        int p = idx / CTXD, k = idx - p * CTXD;
        float s = 0.f;
        for (int d = 0; d < 64; d++)
            s += ideal_w[p * 128 + 64 + d] * ctx_w[d * CTXD + k];
        g_M[idx] = s;
    }
    if (idx < NPR) {
        float s = ideal_b[idx];
        for (int d = 0; d < 64; d++)
            s += ideal_w[idx * 128 + 64 + d] * ctx_b[d];
        g_lb[idx] = s;
    }
}

// ---------------- kB1: prime logits (via M) + softmax + scalars (2 rows/lane) ----------------
#define B1_M    0        // 1920 f
#define B1_IDWT 1920     // 160 ull = 320 f
#define B1_PE   2240     // 160 ull
#define B1_PREV 2560     // 32 ull
#define B1_LB   2624     // 8
#define B1_PART 2632     // 4
#define SMEM_B1_BYTES (2640 * 4)

__global__ __launch_bounds__(128, 2)
void kB1(const float* __restrict__ theta, const float* __restrict__ context,
         const float* __restrict__ ideal_w,
         const float* __restrict__ prime_embeds, const float* __restrict__ prev_ideal,
         const float* __restrict__ freq_w, const float* __restrict__ freq_b,
         float* __restrict__ out) {
    extern __shared__ float smem[];
    const int tid = threadIdx.x, lane = tid & 31, wrp = tid >> 5;

    float* Ms = smem + B1_M;
    ull* idwt = (ull*)(smem + B1_IDWT);
    ull* pe_s = (ull*)(smem + B1_PE);
    ull* prev_s = (ull*)(smem + B1_PREV);
    float* s_lb = smem + B1_LB;
    float* s_part = smem + B1_PART;

    for (int idx = tid; idx < NPR * CTXD; idx += 128) Ms[idx] = g_M[idx];
    for (int idx = tid; idx < 160; idx += 128) {
        int p = idx >> 5, j = idx & 31;
        idwt[idx] = pack2(ideal_w[p * 128 + j], ideal_w[p * 128 + j + 32]);
        pe_s[idx] = pack2(prime_embeds[p * 64 + j], prime_embeds[p * 64 + j + 32]);
    }
    if (tid < 32) prev_s[tid] = pack2(prev_ideal[tid], prev_ideal[tid + 32]);
    if (tid < NPR) s_lb[tid] = g_lb[tid];
    __syncthreads();

    const float fwv = freq_w[0], fbv = freq_b[0];
    float* out_rs = out + (size_t)4 * B_N * 64;
    float* out_om = out_rs + B_N;
    float* out_pw = out_om + B_N;

    const int u = blockIdx.x * 4 + wrp;
    float stress_total = 0.f;
    if (u < 1024) {
        const int r0 = u * 64 + lane, r1 = r0 + 32;

        float lg0[NPR], lg1[NPR];
#pragma unroll
        for (int p = 0; p < NPR; p++) { lg0[p] = s_lb[p]; lg1[p] = s_lb[p]; }
        const float4* x0v = (const float4*)(context + (size_t)r0 * CTXD);
        const float4* x1v = (const float4*)(context + (size_t)r1 * CTXD);
#pragma unroll 4
        for (int k4 = 0; k4 < 96; k4++) {
            float4 a0 = x0v[k4], a1 = x1v[k4];
#pragma unroll
            for (int p = 0; p < NPR; p++) {
                float4 m = ((const float4*)(Ms + p * CTXD))[k4];
                lg0[p] += m.x * a0.x + m.y * a0.y + m.z * a0.z + m.w * a0.w;
                lg1[p] += m.x * a1.x + m.y * a1.y + m.z * a1.z + m.w * a1.w;
            }
        }

        ull th0[32], th1[32];
        load_row_pairs(theta + (size_t)r0 * 64, th0);
        load_row_pairs(theta + (size_t)r1 * 64, th1);
#pragma unroll
        for (int p5 = 0; p5 < NPR; p5++) {
            ull a = 0, b = 0;
#pragma unroll
            for (int j = 0; j < 32; j++) {
                ull w = idwt[p5 * 32 + j];
                fma2(a, w, th0[j]);
                fma2(b, w, th1[j]);
            }
            lg0[p5] += hadd2(a);
            lg1[p5] += hadd2(b);
        }

        float pw0[NPR], pw1[NPR];
        {
            float m0 = lg0[0], m1 = lg1[0];
#pragma unroll
            for (int p = 1; p < NPR; p++) { m0 = fmaxf(m0, lg0[p]); m1 = fmaxf(m1, lg1[p]); }
            float s0 = 0.f, s1 = 0.f;
#pragma unroll
            for (int p = 0; p < NPR; p++) {
                pw0[p] = __expf(lg0[p] - m0); s0 += pw0[p];
                pw1[p] = __expf(lg1[p] - m1); s1 += pw1[p];
            }
            float i0 = __fdividef(1.f, s0), i1 = __fdividef(1.f, s1);
#pragma unroll
            for (int p = 0; p < NPR; p++) {
                pw0[p] *= i0; pw1[p] *= i1;
                out_pw[(size_t)r0 * NPR + p] = pw0[p];
                out_pw[(size_t)r1 * NPR + p] = pw1[p];
            }
        }

        float str0 = 0.f, nth0 = 0.f, nti0 = 0.f, rd0 = 0.f, f20 = 0.f;
        float str1 = 0.f, nth1 = 0.f, nti1 = 0.f, rd1 = 0.f, f21 = 0.f;
#pragma unroll
        for (int j = 0; j < 32; j++) {
            float2 pv = unpack2(prev_s[j]);
            float2 pe0 = unpack2(pe_s[0 * 32 + j]);
            float2 pe1 = unpack2(pe_s[1 * 32 + j]);
            float2 pe2 = unpack2(pe_s[2 * 32 + j]);
            float2 pe3 = unpack2(pe_s[3 * 32 + j]);
            float2 pe4 = unpack2(pe_s[4 * 32 + j]);
            {
                float tix = pw0[0] * pe0.x + pw0[1] * pe1.x + pw0[2] * pe2.x
                          + pw0[3] * pe3.x + pw0[4] * pe4.x;
                float tiy = pw0[0] * pe0.y + pw0[1] * pe1.y + pw0[2] * pe2.y
                          + pw0[3] * pe3.y + pw0[4] * pe4.y;
                float2 t = unpack2(th0[j]);
                float dx = t.x - tix, dy = t.y - tiy;
                str0 += dx * dx + dy * dy;
                nth0 += t.x * t.x + t.y * t.y;
                nti0 += tix * tix + tiy * tiy;
                rd0  += t.x * tix + t.y * tiy;
                float px = tix - pv.x, py = tiy - pv.y;
                f20 += px * px + py * py;
            }
            {
                float tix = pw1[0] * pe0.x + pw1[1] * pe1.x + pw1[2] * pe2.x
                          + pw1[3] * pe3.x + pw1[4] * pe4.x;
                float tiy = pw1[0] * pe0.y + pw1[1] * pe1.y + pw1[2] * pe2.y
                          + pw1[3] * pe3.y + pw1[4] * pe4.y;
                float2 t = unpack2(th1[j]);
                float dx = t.x - tix, dy = t.y - tiy;
                str1 += dx * dx + dy * dy;
                nth1 += t.x * t.x + t.y * t.y;
                nti1 += tix * tix + tiy * tiy;
                rd1  += t.x * tix + t.y * tiy;
                float px = tix - pv.x, py = tiy - pv.y;
                f21 += px * px + py * py;
            }
        }
        {
            float it0 = __fdividef(1.f, sqrtf(nth0) + EPSV);
            float ii0 = __fdividef(1.f, sqrtf(nti0) + EPSV);
            out_rs[r0] = __fdividef(rd0 * it0 * ii0,
                                    fmaxf(sqrtf(nth0) * it0 * sqrtf(nti0) * ii0, EPSV));
            float fr0 = sqrtf(f20);
            out_om[r0] = ftanh(fr0 * fwv + fbv) * (1.0f + 0.1f * __sinf(fr0));
            float it1 = __fdividef(1.f, sqrtf(nth1) + EPSV);
            float ii1 = __fdividef(1.f, sqrtf(nti1) + EPSV);
            out_rs[r1] = __fdividef(rd1 * it1 * ii1,
                                    fmaxf(sqrtf(nth1) * it1 * sqrtf(nti1) * ii1, EPSV));
            float fr1 = sqrtf(f21);
            out_om[r1] = ftanh(fr1 * fwv + fbv) * (1.0f + 0.1f * __sinf(fr1));
        }
        stress_total = str0 + str1;
    }

    float ws = wsum(stress_total);
    if (lane == 0) s_part[wrp] = ws;
    __syncthreads();
    if (tid == 0) {
        g_part[blockIdx.x] = (s_part[0] + s_part[1]) + (s_part[2] + s_part[3]);
    }
}

// ---------------- kB2a: emotion MLP -> out_e = relu(..) + 0.001*stress ----------------
#define B2A_W1  0        // 4096 ull
#define B2A_W2  8192     // 4096 ull
#define B2A_B1  16384    // 128
#define B2A_B2  16512    // 64
#define B2A_STC 16576    // 1
#define SMEM_B2A_BYTES (16580 * 4)

__global__ __launch_bounds__(128, 3)
void kB2a(const float* __restrict__ theta,
          const float* __restrict__ emo_w1, const float* __restrict__ emo_b1,
          const float* __restrict__ emo_w2, const float* __restrict__ emo_b2,
          float* __restrict__ out) {
    extern __shared__ float smem[];
    const int tid = threadIdx.x, lane = tid & 31, wrp = tid >> 5;
    ull* w1i = (ull*)(smem + B2A_W1);
    ull* w2i = (ull*)(smem + B2A_W2);
    float* s_b1 = smem + B2A_B1;
    float* s_b2 = smem + B2A_B2;
    float* s_stc = smem + B2A_STC;

    for (int idx = tid; idx < 4096; idx += 128) {
        int oi = idx & 7, j = (idx >> 3) & 31, og = idx >> 8;
        int o = og * 8 + oi;
        w1i[idx] = pack2(emo_w1[o * 64 + j], emo_w1[o * 64 + j + 32]);
    }
    for (int idx = tid; idx < 4096; idx += 128) {
        int di = idx & 31, kh = idx >> 5;
        w2i[idx] = pack2(emo_w2[di * 128 + kh], emo_w2[(di + 32) * 128 + kh]);
    }
    if (tid < 128) s_b1[tid] = emo_b1[tid];
    if (tid < 64) s_b2[tid] = emo_b2[tid];
    if (tid == 0) {
        float s = 0.f;
        for (int b = 0; b < NPART; b++) s += g_part[b];
        s_stc[0] = 0.001f * s;
    }
    __syncthreads();
    const float stc = s_stc[0];

    float* out_e = out + (size_t)3 * B_N * 64;

#pragma unroll 1
    for (int u = blockIdx.x * 4 + wrp; u < 2048; u += 444 * 4) {
        const int r = u * 32 + lane;
        const size_t ro = (size_t)r * 64;

        ull th_p[32];
        load_row_pairs(theta + ro, th_p);

        ull e_acc[32];
#pragma unroll
        for (int di = 0; di < 32; di++) e_acc[di] = pack2(s_b2[di], s_b2[di + 32]);
#pragma unroll 1
        for (int og = 0; og < 16; og++) {
            const ulonglong2* w1v = (const ulonglong2*)(w1i + og * 256);
            ull a0 = 0, a1 = 0, a2 = 0, a3 = 0, a4 = 0, a5 = 0, a6 = 0, a7 = 0;
#pragma unroll
            for (int j = 0; j < 32; j++) {
                ulonglong2 p0 = w1v[j * 4 + 0], p1 = w1v[j * 4 + 1];
                ulonglong2 p2 = w1v[j * 4 + 2], p3 = w1v[j * 4 + 3];
                ull t = th_p[j];
                fma2(a0, p0.x, t); fma2(a1, p0.y, t);
                fma2(a2, p1.x, t); fma2(a3, p1.y, t);
                fma2(a4, p2.x, t); fma2(a5, p2.y, t);
                fma2(a6, p3.x, t); fma2(a7, p3.y, t);
            }
            float t8[8];
            t8[0] = ftanh(hadd2(a0) + s_b1[og * 8 + 0]);
            t8[1] = ftanh(hadd2(a1) + s_b1[og * 8 + 1]);
            t8[2] = ftanh(hadd2(a2) + s_b1[og * 8 + 2]);
            t8[3] = ftanh(hadd2(a3) + s_b1[og * 8 + 3]);
            t8[4] = ftanh(hadd2(a4) + s_b1[og * 8 + 4]);
            t8[5] = ftanh(hadd2(a5) + s_b1[og * 8 + 5]);
            t8[6] = ftanh(hadd2(a6) + s_b1[og * 8 + 6]);
            t8[7] = ftanh(hadd2(a7) + s_b1[og * 8 + 7]);
#pragma unroll
            for (int k = 0; k < 8; k++) {
                ull tt = pack2(t8[k], t8[k]);
                const ulonglong2* w2v = (const ulonglong2*)(w2i + (og * 8 + k) * 32);
#pragma unroll
                for (int di2 = 0; di2 < 16; di2++) {
                    ulonglong2 q = w2v[di2];
                    fma2(e_acc[di2 * 2 + 0], q.x, tt);
                    fma2(e_acc[di2 * 2 + 1], q.y, tt);
                }
            }
        }
        float4* ep = (float4*)(out_e + ro);
#pragma unroll
        for (int k = 0; k < 8; k++) {
            float2 v0 = unpack2(e_acc[k * 4 + 0]);
            float2 v1 = unpack2(e_acc[k * 4 + 1]);
            float2 v2 = unpack2(e_acc[k * 4 + 2]);
            float2 v3 = unpack2(e_acc[k * 4 + 3]);
            ep[k]     = make_float4(fmaxf(v0.x, 0.f) + stc, fmaxf(v1.x, 0.f) + stc,
                                    fmaxf(v2.x, 0.f) + stc, fmaxf(v3.x, 0.f) + stc);
            ep[8 + k] = make_float4(fmaxf(v0.y, 0.f) + stc, fmaxf(v1.y, 0.f) + stc,
                                    fmaxf(v2.y, 0.f) + stc, fmaxf(v3.y, 0.f) + stc);
        }
    }
}

// ---------------- kDF v4: fused GRU, e/h ROLE-split across half-warps ----------------
// Lane kh=0 holds full e-row and computes the 6 e-sums; kh=1 holds full h-row and
// computes the 6 h-sums — into the SAME accumulator registers. 6 shfl_xor(16)
// exchange roles. Epilogue: kh=0 finalizes lo outputs (d), kh=1 hi (d+32).
// smem: e-weights [(d*32+j)*6+s] (s: r_lo,r_hi,z_lo,z_hi,n_lo,n_hi), h at +6144.
#define DF_W   0         // 12288 ull = 24576 f
#define DF_CST 24576     // 192
#define DF_RES 24768     // 192
#define DF_OM  24960     // 192
#define DF_BHH 25152     // 192
#define SMEM_DF_BYTES (25344 * 4)

__global__ __launch_bounds__(256, 2)
void kDF(const float* __restrict__ wih_f, const float* __restrict__ whh_f,
         const float* __restrict__ bhh_f,
         const float* __restrict__ wih_r, const float* __restrict__ whh_r,
         const float* __restrict__ bhh_r,
         const float* __restrict__ h_prev, const float* __restrict__ theta,
         float* __restrict__ out) {
    extern __shared__ float smem[];
    const int tid = threadIdx.x, lane = tid & 31, wrp = tid >> 5;
    const int dir = blockIdx.x & 1, u = blockIdx.x >> 1;
    const int kh = lane >> 4, ln = lane & 15;

    ull* wEH = (ull*)(smem + DF_W);
    float* scst = smem + DF_CST;
    float* sres = smem + DF_RES;
    float* som  = smem + DF_OM;
    float* sbhh = smem + DF_BHH;

    const float* wih = dir ? wih_r : wih_f;
    const float* whh = dir ? whh_r : whh_f;
    const float* bhh = dir ? bhh_r : bhh_f;

    // fill: e-block [0,6144), h-block [6144,12288)
    for (int idx = tid; idx < 12288; idx += 256) {
        int blk = idx >= 6144;
        int li = blk ? idx - 6144 : idx;
        int s = li % 6, t = li / 6;
        int j = t & 31, d = t >> 5;
        int o = (s >> 1) * 64 + (s & 1) * 32 + d;
        wEH[idx] = blk ? pack2(whh[o * 64 + j], whh[o * 64 + 32 + j])
                       : pack2(wih[o * 130 + 64 + j], wih[o * 130 + 96 + j]);
    }
    for (int i = tid; i < 192; i += 256) {
        scst[i] = dir ? g_const_r[i] : g_const_f[i];
        sres[i] = wih[i * 130 + 128];
        som[i]  = wih[i * 130 + 129];
        sbhh[i] = bhh[i];
    }
    __syncthreads();

    const float* hpd = h_prev + (size_t)dir * B_N * 64;
    const float* out_e = out + (size_t)3 * B_N * 64;
    const float* out_rs = out + (size_t)4 * B_N * 64;
    const float* out_om = out_rs + B_N;
    float* out_t = out;
    float* out_h = out + (size_t)(1 + dir) * B_N * 64;

    const int r = u * 128 + wrp * 16 + ln;
    const size_t ro = (size_t)r * 64;

    // role-dependent input row: kh=0 -> e_theta row, kh=1 -> h_prev row
    ull x_p[32];
    load_row_pairs((kh ? hpd : out_e) + ro, x_p);
    const float res = out_rs[r], om = out_om[r];

    // role-dependent weight base
    const ulonglong2* wbase = (const ulonglong2*)(wEH + kh * 6144);

#pragma unroll 1
    for (int d = 0; d < 32; d++) {
        const ulonglong2* w = wbase + (size_t)d * 96;
        ull A0 = 0, A1 = 0, A2 = 0, A3 = 0, A4 = 0, A5 = 0;
#pragma unroll
        for (int j = 0; j < 32; j++) {
            ulonglong2 q0 = w[j * 3 + 0], q1 = w[j * 3 + 1], q2 = w[j * 3 + 2];
            ull x = x_p[j];
            fma2(A0, q0.x, x); fma2(A1, q0.y, x);
            fma2(A2, q1.x, x); fma2(A3, q1.y, x);
            fma2(A4, q2.x, x); fma2(A5, q2.y, x);
        }
        float a0 = hadd2(A0), a1 = hadd2(A1), a2 = hadd2(A2);
        float a3 = hadd2(A3), a4 = hadd2(A4), a5 = hadd2(A5);
        // exchange: partner holds the other role's sums in the same regs
        float p0 = __shfl_xor_sync(0xffffffffu, a0, 16);
        float p1 = __shfl_xor_sync(0xffffffffu, a1, 16);
        float p2 = __shfl_xor_sync(0xffffffffu, a2, 16);
        float p3 = __shfl_xor_sync(0xffffffffu, a3, 16);
        float p4 = __shfl_xor_sync(0xffffffffu, a4, 16);
        float p5 = __shfl_xor_sync(0xffffffffu, a5, 16);

        // kh=0: e = own (lo slots 0,2,4), h = partner (lo slots)
        // kh=1: h = own (hi slots 1,3,5), e = partner (hi slots)
        float e_r = kh ? p1 : a0;
        float e_z = kh ? p3 : a2;
        float e_n = kh ? p5 : a4;
        float h_r = kh ? a1 : p0;
        float h_z = kh ? a3 : p2;
        float h_n = kh ? a5 : p4;

        const int hb = kh << 5;
        const int i_r = hb + d, i_z = 64 + hb + d, i_n = 128 + hb + d;
        float ir  = e_r + scst[i_r] + res * sres[i_r] + om * som[i_r];
        float iz  = e_z + scst[i_z] + res * sres[i_z] + om * som[i_z];
        float inx = e_n + scst[i_n] + res * sres[i_n] + om * som[i_n];
        float hr = h_r + sbhh[i_r];
        float hz = h_z + sbhh[i_z];
        float hn = h_n + sbhh[i_n];
        float hv = hpd[ro + hb + d];
        float rg = sigm(ir + hr), zg = sigm(iz + hz);
        float ng = ftanh(inx + rg * hn);
        float o = (1.f - zg) * ng + zg * hv;
        out_h[ro + hb + d] = o;
        if (dir == 0) {
            out_t[ro + hb + d] = 0.3f * theta[ro + hb + d] + 0.7f * o;
        }
    }
}

extern "C" void kernel_launch(void* const* d_in, const int* in_sizes, int n_in,
                              void* d_out, int out_size) {
    const float* theta   = (const float*)d_in[0];
    const float* context = (const float*)d_in[1];
    const float* h_prev  = (const float*)d_in[2];
    const float* memory  = (const float*)d_in[3];
    const float* tw      = (const float*)d_in[4];
    const float* ipw     = (const float*)d_in[5];
    const float* ipb     = (const float*)d_in[6];
    const float* ow      = (const float*)d_in[7];
    const float* ob      = (const float*)d_in[8];
    const float* emo_w1  = (const float*)d_in[9];
    const float* emo_b1  = (const float*)d_in[10];
    const float* emo_w2  = (const float*)d_in[11];
    const float* emo_b2  = (const float*)d_in[12];
    const float* pe      = (const float*)d_in[13];
    const float* ctx_w   = (const float*)d_in[14];
    const float* ctx_b   = (const float*)d_in[15];
    const float* ideal_w = (const float*)d_in[16];
    const float* ideal_b = (const float*)d_in[17];
    const float* wih_f   = (const float*)d_in[18];
    const float* whh_f   = (const float*)d_in[19];
    const float* bih_f   = (const float*)d_in[20];
    const float* bhh_f   = (const float*)d_in[21];
    const float* wih_r   = (const float*)d_in[22];
    const float* whh_r   = (const float*)d_in[23];
    const float* bih_r   = (const float*)d_in[24];
    const float* bhh_r   = (const float*)d_in[25];
    const float* freq_w  = (const float*)d_in[26];
    const float* freq_b  = (const float*)d_in[27];
    const float* prev_i  = (const float*)d_in[28];
    float* out = (float*)d_out;

    static bool attr_set = false;
    if (!attr_set) {
        cudaFuncSetAttribute(kB1, cudaFuncAttributeMaxDynamicSharedMemorySize, SMEM_B1_BYTES);
        cudaFuncSetAttribute(kB2a, cudaFuncAttributeMaxDynamicSharedMemorySize, SMEM_B2A_BYTES);
        cudaFuncSetAttribute(kDF, cudaFuncAttributeMaxDynamicSharedMemorySize, SMEM_DF_BYTES);
        attr_set = true;
    }

    kA<<<1, 192>>>(memory, tw, ipw, ipb, ow, ob, wih_f, bih_f, wih_r, bih_r);
    kM<<<15, 128>>>(ideal_w, ideal_b, ctx_w, ctx_b);
    kB1<<<296, 128, SMEM_B1_BYTES>>>(theta, context, ideal_w,
                                     pe, prev_i, freq_w, freq_b, out);
    kB2a<<<444, 128, SMEM_B2A_BYTES>>>(theta, emo_w1, emo_b1, emo_w2, emo_b2, out);
    kDF<<<1024, 256, SMEM_DF_BYTES>>>(wih_f, whh_f, bhh_f, wih_r, whh_r, bhh_r,
                                      h_prev, theta, out);
}